// round 6
// baseline (speedup 1.0000x reference)
#include <cuda_runtime.h>
#include <cstdint>

// ROI Align, P=7, S=2, SCALE=0.125
// x: (8, 256, 100, 100) fp32   rois: (512, 5) fp32   out: (512, 256, 7, 7) fp32
//
// 1) transpose_kernel: NCHW -> NHWC-64  (x_t[b][cg][y*W+x][64c], fp32, 82MB)
// 2) roi_nhwc: block=(roi, cg64). Warp = 64 channels of one bin; every tap is
//    one LDG.64 of 256 contiguous bytes (2 wavefronts) instead of ~5 scattered.
//    Geometry inline per block; outputs staged in smem, written coalesced.

#define C_    256
#define H_    100
#define W_    100
#define HW_   10000
#define R_    512
#define CG    4
#define CPG   64
#define SLAB  (HW_ * CPG)       // floats per (b,cg) slab = 640000

__device__ float g_xt[8 * CG * SLAB];   // 81.92 MB scratch

__device__ __forceinline__ void axis_terms(float c, int L,
                                           int& lo, int& hi,
                                           float& wlo, float& whi) {
    bool valid = (c > -1.0f) && (c < (float)L);
    float cc = fminf(fmaxf(c, 0.0f), (float)(L - 1));
    int l = (int)floorf(cc);
    if (l > L - 1) l = L - 1;
    int h = min(l + 1, L - 1);
    float frac = cc - (float)l;
    lo = l; hi = h;
    wlo = valid ? (1.0f - frac) : 0.0f;
    whi = valid ? frac : 0.0f;
}

// block = (b, cg, y): stage 64 channels x 100 x in smem, write channel-major.
__global__ void __launch_bounds__(256)
transpose_kernel(const float* __restrict__ x) {
    __shared__ float s[CPG][W_ + 1];   // stride 101 -> conflict-free column reads

    int blk = blockIdx.x;
    int y   = blk % H_;
    int t2  = blk / H_;
    int cg  = t2 & (CG - 1);
    int b   = t2 >> 2;

    const int tid  = threadIdx.x;
    const int warp = tid >> 5;
    const int lane = tid & 31;

    const float* src = x + ((size_t)(b * C_ + cg * CPG)) * HW_ + y * W_;
#pragma unroll
    for (int c = warp; c < CPG; c += 8)
        for (int xx = lane; xx < W_; xx += 32)
            s[c][xx] = __ldg(src + c * HW_ + xx);
    __syncthreads();

    float* dst = g_xt + ((size_t)(b * CG + cg)) * SLAB + (size_t)y * (W_ * CPG);
#pragma unroll
    for (int i = tid; i < CPG * W_; i += 256) {
        int xx = i >> 6;
        int c  = i & 63;
        dst[xx * CPG + c] = s[c][xx];
    }
}

__device__ __forceinline__ float2 hrow(const float2* __restrict__ p, int dx,
                                       float w0, float w1, float w2, float w3) {
    float2 c0 = __ldg(p);
    float2 c1 = __ldg(p + 32);
    float2 c2 = __ldg(p + dx);
    float2 c3 = __ldg(p + dx + 32);
    float2 h;
    h.x = w0 * c0.x + w1 * c1.x + w2 * c2.x + w3 * c3.x;
    h.y = w0 * c0.y + w1 * c1.y + w2 * c2.y + w3 * c3.y;
    return h;
}

// block = (roi, cg64), 256 threads / 8 warps; warp handles bins w, w+8, ...
__global__ void __launch_bounds__(256)
roi_nhwc(const float* __restrict__ rois, float* __restrict__ out) {
    __shared__ int4  sg[28];        // [0..13] y: {lo*3200, hi*3200, wy0*.25, wy1*.25}
                                    // [14..27] x: {xb*32, wx0, wx1, -} (float2 units)
    __shared__ float sout[CPG * 49];

    const int r   = blockIdx.x >> 2;
    const int cg  = blockIdx.x & 3;
    const int tid = threadIdx.x;

    const float* roi = rois + (size_t)r * 5;
    float r0 = __ldg(roi + 0);
    float r1 = __ldg(roi + 1);
    float r2 = __ldg(roi + 2);
    float r3 = __ldg(roi + 3);
    float r4 = __ldg(roi + 4);

    const int b = (int)r0;
    const float sx = r1 * 0.125f - 0.5f;
    const float sy = r2 * 0.125f - 0.5f;
    const float bw = (r3 * 0.125f - 0.5f - sx) * (1.0f / 7.0f);
    const float bh = (r4 * 0.125f - 0.5f - sy) * (1.0f / 7.0f);

    if (tid < 14) {
        int s = tid;
        float pos = fmaf((float)(s >> 1) + ((s & 1) ? 0.75f : 0.25f), bh, sy);
        int lo, hi; float w0, w1;
        axis_terms(pos, H_, lo, hi, w0, w1);
        sg[s] = make_int4(lo * (W_ * CPG / 2), hi * (W_ * CPG / 2),
                          __float_as_int(w0 * 0.25f), __float_as_int(w1 * 0.25f));
    } else if (tid >= 16 && tid < 30) {
        int s2 = tid - 16;
        float pos = fmaf((float)(s2 >> 1) + ((s2 & 1) ? 0.75f : 0.25f), bw, sx);
        int lo, hi; float w0, w1;
        axis_terms(pos, W_, lo, hi, w0, w1);
        int xb; float v0, v1;
        if (lo == W_ - 1) { xb = W_ - 2; v0 = 0.0f; v1 = w0 + w1; }
        else              { xb = lo;     v0 = w0;   v1 = w1; }
        sg[14 + s2] = make_int4(xb * (CPG / 2),
                                __float_as_int(v0), __float_as_int(v1), 0);
    }
    __syncthreads();

    const int warp = tid >> 5;
    const int lane = tid & 31;
    const float2* base = (const float2*)(g_xt + ((size_t)(b * CG + cg)) * SLAB) + lane;

    for (int bin = warp; bin < 49; bin += 8) {
        int ph = (bin * 147) >> 10;         // bin / 7 for bin < 49
        int pw = bin - ph * 7;

        int4 gy0 = sg[2 * ph];
        int4 gy1 = sg[2 * ph + 1];
        int4 gx0 = sg[14 + 2 * pw];
        int4 gx1 = sg[14 + 2 * pw + 1];

        const float2* p0 = base + gy0.x + gx0.x;
        const float2* p1 = base + gy0.y + gx0.x;
        const float2* p2 = base + gy1.x + gx0.x;
        const float2* p3 = base + gy1.y + gx0.x;
        const int dx = gx1.x - gx0.x;

        const float wx0 = __int_as_float(gx0.y), wx1 = __int_as_float(gx0.z);
        const float wx2 = __int_as_float(gx1.y), wx3 = __int_as_float(gx1.z);

        float2 h0 = hrow(p0, dx, wx0, wx1, wx2, wx3);
        float2 h1 = hrow(p1, dx, wx0, wx1, wx2, wx3);
        float2 h2 = hrow(p2, dx, wx0, wx1, wx2, wx3);
        float2 h3 = hrow(p3, dx, wx0, wx1, wx2, wx3);

        const float wyA0 = __int_as_float(gy0.z), wyA1 = __int_as_float(gy0.w);
        const float wyB0 = __int_as_float(gy1.z), wyB1 = __int_as_float(gy1.w);

        float rx = wyA0 * h0.x + wyA1 * h1.x + wyB0 * h2.x + wyB1 * h3.x;
        float ry = wyA0 * h0.y + wyA1 * h1.y + wyB0 * h2.y + wyB1 * h3.y;

        sout[(2 * lane) * 49 + bin]     = rx;
        sout[(2 * lane + 1) * 49 + bin] = ry;
    }
    __syncthreads();

    float* op = out + ((size_t)r * C_ + cg * CPG) * 49;
#pragma unroll
    for (int i = tid; i < CPG * 49; i += 256)
        op[i] = sout[i];
}

extern "C" void kernel_launch(void* const* d_in, const int* in_sizes, int n_in,
                              void* d_out, int out_size) {
    const float* x    = (const float*)d_in[0];
    const float* rois = (const float*)d_in[1];
    float* out = (float*)d_out;

    transpose_kernel<<<8 * CG * H_, 256>>>(x);
    roi_nhwc<<<R_ * CG, 256>>>(rois, out);
}

// round 8
// speedup vs baseline: 1.3721x; 1.3721x over previous
#include <cuda_runtime.h>
#include <cuda_fp16.h>
#include <cstdint>

// ROI Align, P=7, S=2, SCALE=0.125
// x: (8, 256, 100, 100) fp32   rois: (512, 5) fp32   out: (512, 256, 7, 7) fp32
//
// 1) transpose_kernel: NCHW fp32 -> NHWC-128 fp16 slabs
//    g_xt[b][cg2][y*W+x][128ch], 41MB. Conflict-free smem, uint4 stores.
// 2) roi_fp16: block=(roi, cg2). Warp = 128 channels of one bin; each tap is
//    one LDG.64 (4 fp16 ch/lane, 256B/warp). fp32 accumulation.

#define C_    256
#define H_    100
#define W_    100
#define HW_   10000
#define R_    512
#define CPG   128                  // channels per slab
#define NCG   2                    // slabs per image
#define PIXU2 (CPG / 4)            // uint2 per pixel = 32
#define ROWU2 (W_ * PIXU2)         // uint2 per row = 3200

// fp16 slabs as uint array: 8 * 2 * 10000 * 64 uints = 40.96 MB
__device__ unsigned int g_xt[8 * NCG * HW_ * (CPG / 2)];

__device__ __forceinline__ void axis_terms(float c, int L,
                                           int& lo, int& hi,
                                           float& wlo, float& whi) {
    bool valid = (c > -1.0f) && (c < (float)L);
    float cc = fminf(fmaxf(c, 0.0f), (float)(L - 1));
    int l = (int)floorf(cc);
    if (l > L - 1) l = L - 1;
    int h = min(l + 1, L - 1);
    float frac = cc - (float)l;
    lo = l; hi = h;
    wlo = valid ? (1.0f - frac) : 0.0f;
    whi = valid ? frac : 0.0f;
}

// block = (b, cg, y): 128 channels x 100 px -> fp16 channel-major.
__global__ void __launch_bounds__(256)
transpose_kernel(const float* __restrict__ x) {
    __shared__ unsigned int s2[W_ * 65];   // [xx][c2] half2, stride 65 -> bank-free

    const int blk = blockIdx.x;
    const int y   = blk % H_;
    const int t2  = blk / H_;
    const int cg  = t2 & (NCG - 1);
    const int b   = t2 >> 1;
    const int tid = threadIdx.x;

    const float* src = x + ((size_t)(b * C_ + cg * CPG)) * HW_ + y * W_;

    // phase 1: 64 channel-pairs x 100 px; coalesced loads, conflict-free STS
    for (int i = tid; i < 64 * W_; i += 256) {
        int c2 = i / W_;
        int xx = i - c2 * W_;
        float f0 = __ldg(src + (2 * c2) * HW_ + xx);
        float f1 = __ldg(src + (2 * c2 + 1) * HW_ + xx);
        __half2 h = __floats2half2_rn(f0, f1);
        s2[xx * 65 + c2] = *(unsigned int*)&h;
    }
    __syncthreads();

    // phase 2: 100 px x 16 uint4; STG.128 coalesced
    unsigned int* dst = g_xt + ((size_t)((b * NCG + cg) * HW_) + (size_t)y * W_) * (CPG / 2);
    for (int j = tid; j < W_ * 16; j += 256) {
        int px = j >> 4;
        int q  = j & 15;
        const unsigned int* sp = s2 + px * 65 + 4 * q;
        uint4 v = make_uint4(sp[0], sp[1], sp[2], sp[3]);
        *(uint4*)(dst + px * 64 + 4 * q) = v;
    }
}

__device__ __forceinline__ float4 hrow(const uint2* __restrict__ p, int dx,
                                       float w0, float w1, float w2, float w3) {
    uint2 t0 = __ldg(p);
    uint2 t1 = __ldg(p + PIXU2);
    uint2 t2 = __ldg(p + dx);
    uint2 t3 = __ldg(p + dx + PIXU2);

    float2 a0 = __half22float2(*(__half2*)&t0.x), a1 = __half22float2(*(__half2*)&t0.y);
    float2 b0 = __half22float2(*(__half2*)&t1.x), b1 = __half22float2(*(__half2*)&t1.y);
    float2 c0 = __half22float2(*(__half2*)&t2.x), c1 = __half22float2(*(__half2*)&t2.y);
    float2 d0 = __half22float2(*(__half2*)&t3.x), d1 = __half22float2(*(__half2*)&t3.y);

    float4 h;
    h.x = fmaf(w0, a0.x, fmaf(w1, b0.x, fmaf(w2, c0.x, w3 * d0.x)));
    h.y = fmaf(w0, a0.y, fmaf(w1, b0.y, fmaf(w2, c0.y, w3 * d0.y)));
    h.z = fmaf(w0, a1.x, fmaf(w1, b1.x, fmaf(w2, c1.x, w3 * d1.x)));
    h.w = fmaf(w0, a1.y, fmaf(w1, b1.y, fmaf(w2, c1.y, w3 * d1.y)));
    return h;
}

// block = (roi, cg2), 256 threads / 8 warps over 49 bins.
__global__ void __launch_bounds__(256)
roi_fp16(const float* __restrict__ rois, float* __restrict__ out) {
    __shared__ int4  sg[28];          // y: {lo*3200, hi*3200, wy0*.25, wy1*.25}
                                      // x: {xb*32, wx0, wx1, -}   (uint2 units)
    __shared__ float sout[CPG * 49];  // 25.1 KB

    const int r   = blockIdx.x >> 1;
    const int cg  = blockIdx.x & 1;
    const int tid = threadIdx.x;

    const float* roi = rois + (size_t)r * 5;
    float r0 = __ldg(roi + 0);
    float r1 = __ldg(roi + 1);
    float r2 = __ldg(roi + 2);
    float r3 = __ldg(roi + 3);
    float r4 = __ldg(roi + 4);

    const int b = (int)r0;
    const float sx = r1 * 0.125f - 0.5f;
    const float sy = r2 * 0.125f - 0.5f;
    const float bw = (r3 * 0.125f - 0.5f - sx) * (1.0f / 7.0f);
    const float bh = (r4 * 0.125f - 0.5f - sy) * (1.0f / 7.0f);

    if (tid < 14) {
        int s = tid;
        float pos = fmaf((float)(s >> 1) + ((s & 1) ? 0.75f : 0.25f), bh, sy);
        int lo, hi; float w0, w1;
        axis_terms(pos, H_, lo, hi, w0, w1);
        sg[s] = make_int4(lo * ROWU2, hi * ROWU2,
                          __float_as_int(w0 * 0.25f), __float_as_int(w1 * 0.25f));
    } else if (tid >= 16 && tid < 30) {
        int s2 = tid - 16;
        float pos = fmaf((float)(s2 >> 1) + ((s2 & 1) ? 0.75f : 0.25f), bw, sx);
        int lo, hi; float w0, w1;
        axis_terms(pos, W_, lo, hi, w0, w1);
        int xb; float v0, v1;
        if (lo == W_ - 1) { xb = W_ - 2; v0 = 0.0f; v1 = w0 + w1; }
        else              { xb = lo;     v0 = w0;   v1 = w1; }
        sg[14 + s2] = make_int4(xb * PIXU2,
                                __float_as_int(v0), __float_as_int(v1), 0);
    }
    __syncthreads();

    const int warp = tid >> 5;
    const int lane = tid & 31;
    const uint2* base = (const uint2*)g_xt
                      + (size_t)(b * NCG + cg) * (HW_ * PIXU2) + lane;

    for (int bin = warp; bin < 49; bin += 8) {
        int ph = (bin * 147) >> 10;       // bin / 7 for bin < 49
        int pw = bin - ph * 7;

        int4 gy0 = sg[2 * ph];
        int4 gy1 = sg[2 * ph + 1];
        int4 gx0 = sg[14 + 2 * pw];
        int4 gx1 = sg[14 + 2 * pw + 1];

        const uint2* p0 = base + gy0.x + gx0.x;
        const uint2* p1 = base + gy0.y + gx0.x;
        const uint2* p2 = base + gy1.x + gx0.x;
        const uint2* p3 = base + gy1.y + gx0.x;
        const int dx = gx1.x - gx0.x;

        const float wx0 = __int_as_float(gx0.y), wx1 = __int_as_float(gx0.z);
        const float wx2 = __int_as_float(gx1.y), wx3 = __int_as_float(gx1.z);

        float4 h0 = hrow(p0, dx, wx0, wx1, wx2, wx3);
        float4 h1 = hrow(p1, dx, wx0, wx1, wx2, wx3);
        float4 h2 = hrow(p2, dx, wx0, wx1, wx2, wx3);
        float4 h3 = hrow(p3, dx, wx0, wx1, wx2, wx3);

        const float wyA0 = __int_as_float(gy0.z), wyA1 = __int_as_float(gy0.w);
        const float wyB0 = __int_as_float(gy1.z), wyB1 = __int_as_float(gy1.w);

        float* so = sout + (4 * lane) * 49 + bin;
        so[0 * 49] = wyA0 * h0.x + wyA1 * h1.x + wyB0 * h2.x + wyB1 * h3.x;
        so[1 * 49] = wyA0 * h0.y + wyA1 * h1.y + wyB0 * h2.y + wyB1 * h3.y;
        so[2 * 49] = wyA0 * h0.z + wyA1 * h1.z + wyB0 * h2.z + wyB1 * h3.z;
        so[3 * 49] = wyA0 * h0.w + wyA1 * h1.w + wyB0 * h2.w + wyB1 * h3.w;
    }
    __syncthreads();

    float* op = out + ((size_t)r * C_ + cg * CPG) * 49;
#pragma unroll
    for (int i = tid; i < CPG * 49; i += 256)
        op[i] = sout[i];
}

extern "C" void kernel_launch(void* const* d_in, const int* in_sizes, int n_in,
                              void* d_out, int out_size) {
    const float* x    = (const float*)d_in[0];
    const float* rois = (const float*)d_in[1];
    float* out = (float*)d_out;

    transpose_kernel<<<8 * NCG * H_, 256>>>(x);
    roi_fp16<<<R_ * NCG, 256>>>(rois, out);
}